// round 13
// baseline (speedup 1.0000x reference)
#include <cuda_runtime.h>
#include <cuda_bf16.h>
#include <mma.h>

using namespace nvcuda;

#define BB 32
#define NN 1024
#define FF 128
#define HH 64
#define CC 32
#define KK 2
#define NITER 5
#define INV_TEMP 2.0f
#define ROWS (BB*NN)
#define FULLM 0xffffffffu

// WMMA tiling (family-portable HMMA)
#define TMG 128         // rows per block (gcn/aq)
#define LDA 72          // bf16 elems
#define LDB 72
#define LDC_G 72        // f32 elems
#define LDC_A 40
#define SMEM_G2 ((TMG*LDA + 2*64*LDB) * 2)   // 36864 (== Cs bytes)
#define SMEM_A2 ((TMG*LDA + 2*32*LDB) * 2)   // 27648 (Cs 20480 fits)

// k_xw WMMA tiling
#define TMX 128
#define LDX 136
#define LDW 72
#define LDCX 72
#define SMEM_X ((2*TMX*LDX + 2*FF*LDW) * 2)  // 106496

// pool kernel
#define LDP 112
#define SMEM_P (8*32*LDP*4)                  // 114688

__device__ __forceinline__ unsigned short f2bf(float f) {
    return __bfloat16_as_ushort(__float2bfloat16(f));
}
__device__ __forceinline__ float bf2f(unsigned short u) {
    return __bfloat162float(__ushort_as_bfloat16(u));
}
__device__ __forceinline__ unsigned packbf(float a, float b) {
    return (unsigned)f2bf(a) | ((unsigned)f2bf(b) << 16);
}

// ---------------- scratch (device globals; allocation-free) ----------------
__device__ float          g_dY[ROWS*HH];
__device__ float          g_dinv[ROWS];
__device__ unsigned       g_adjb[ROWS*32];
__device__ unsigned       g_adjl[ROWS*32];
__device__ int            g_nz[ROWS];
__device__ float          g_h[ROWS*HH];
__device__ unsigned short g_h_hi[ROWS*HH];
__device__ unsigned short g_h_lo[ROWS*HH];
__device__ float          g_unary[ROWS*CC];
__device__ float          g_e[ROWS*KK];
__device__ float          g_Qa[ROWS*CC];
__device__ float          g_Qb[ROWS*CC];
__device__ float          g_cs[BB*64];
__device__ unsigned short g_AQ_hi[ROWS*CC];
__device__ unsigned short g_AQ_lo[ROWS*CC];
__device__ unsigned short g_dYT_hi[(size_t)BB*64*NN];   // [b][c][n] bf16
__device__ unsigned short g_dYT_lo[(size_t)BB*64*NN];
__device__ unsigned short g_QT_hi[(size_t)BB*32*NN];
__device__ unsigned short g_QT_lo[(size_t)BB*32*NN];

__device__ __forceinline__ const float* qsel(int s) { return s ? g_Qb : g_Qa; }
__device__ __forceinline__ float*       qselw(int s){ return s ? g_Qb : g_Qa; }

// ------------- K1: pack adjacency bits + degree -> dinv ---------------------
__global__ void k_bits(const int* __restrict__ adj) {
    int warp = threadIdx.x >> 5, lane = threadIdx.x & 31;
    int row  = blockIdx.x * 8 + warp;
    const int* ar = adj + (size_t)row * NN;
    unsigned myw = 0;
#pragma unroll
    for (int w = 0; w < 32; w++) {
        unsigned bal = __ballot_sync(FULLM, ar[(w << 5) + lane] != 0);
        if (lane == w) myw = bal;
    }
    g_adjb[row * 32 + lane] = myw;
    int d = __popc(myw);
#pragma unroll
    for (int o = 16; o; o >>= 1) d += __shfl_xor_sync(FULLM, d, o);
    if (lane == 0) g_dinv[row] = rsqrtf((float)d + 1.0f);
}

// ------------- K2: dY = (x @ W_gcn)*dinv via WMMA (hi/lo split both) --------
__global__ void __launch_bounds__(256, 1) k_xw_wmma(const float* __restrict__ x,
                                                    const float* __restrict__ Wg) {
    extern __shared__ char smem[];
    __nv_bfloat16* Ah = (__nv_bfloat16*)smem;      // [TMX][LDX]
    __nv_bfloat16* Al = Ah + TMX * LDX;
    __nv_bfloat16* Bh = Al + TMX * LDX;            // [FF][LDW]
    __nv_bfloat16* Bl = Bh + FF * LDW;
    float* Cs = (float*)smem;                      // alias (epilogue)

    int t = threadIdx.x, w = t >> 5;
    int rowbase = blockIdx.x * TMX;

    for (int i = t; i < FF * HH; i += 256) {
        float v = Wg[i];
        unsigned short hv = f2bf(v);
        int r = i >> 6, c = i & 63;
        Bh[r * LDW + c] = __ushort_as_bfloat16(hv);
        Bl[r * LDW + c] = __ushort_as_bfloat16(f2bf(v - bf2f(hv)));
    }
    {
        const float4* xs = (const float4*)(x + (size_t)rowbase * FF);
        for (int i = t; i < TMX * FF / 4; i += 256) {
            float4 v = xs[i];
            int r = i >> 5, c4 = (i & 31) * 4;
            unsigned short h0 = f2bf(v.x), h1 = f2bf(v.y), h2 = f2bf(v.z), h3 = f2bf(v.w);
            __nv_bfloat16* ah = Ah + r * LDX + c4;
            __nv_bfloat16* al = Al + r * LDX + c4;
            ah[0] = __ushort_as_bfloat16(h0); al[0] = __ushort_as_bfloat16(f2bf(v.x - bf2f(h0)));
            ah[1] = __ushort_as_bfloat16(h1); al[1] = __ushort_as_bfloat16(f2bf(v.y - bf2f(h1)));
            ah[2] = __ushort_as_bfloat16(h2); al[2] = __ushort_as_bfloat16(f2bf(v.z - bf2f(h2)));
            ah[3] = __ushort_as_bfloat16(h3); al[3] = __ushort_as_bfloat16(f2bf(v.w - bf2f(h3)));
        }
    }
    __syncthreads();

    wmma::fragment<wmma::accumulator, 16, 16, 16, float> acc[4];
#pragma unroll
    for (int j = 0; j < 4; j++) wmma::fill_fragment(acc[j], 0.0f);
#pragma unroll
    for (int kt = 0; kt < 8; kt++) {
        wmma::fragment<wmma::matrix_a, 16, 16, 16, __nv_bfloat16, wmma::row_major> ah, al;
        wmma::load_matrix_sync(ah, Ah + (w * 16) * LDX + kt * 16, LDX);
        wmma::load_matrix_sync(al, Al + (w * 16) * LDX + kt * 16, LDX);
#pragma unroll
        for (int j = 0; j < 4; j++) {
            wmma::fragment<wmma::matrix_b, 16, 16, 16, __nv_bfloat16, wmma::row_major> bh, bl;
            wmma::load_matrix_sync(bh, Bh + kt * 16 * LDW + j * 16, LDW);
            wmma::load_matrix_sync(bl, Bl + kt * 16 * LDW + j * 16, LDW);
            wmma::mma_sync(acc[j], ah, bh, acc[j]);
            wmma::mma_sync(acc[j], ah, bl, acc[j]);
            wmma::mma_sync(acc[j], al, bh, acc[j]);
        }
    }
    __syncthreads();
#pragma unroll
    for (int j = 0; j < 4; j++)
        wmma::store_matrix_sync(Cs + (w * 16) * LDCX + j * 16, acc[j], LDCX, wmma::mem_row_major);
    __syncthreads();

    {
        int r2 = t >> 1, half = t & 1;
        int grow = rowbase + r2;
        float di = g_dinv[grow];
        float4* dst = (float4*)&g_dY[(size_t)grow * HH + half * 32];
#pragma unroll
        for (int i = 0; i < 8; i++) {
            const float* c = &Cs[r2 * LDCX + half * 32 + i * 4];
            dst[i] = make_float4(c[0] * di, c[1] * di, c[2] * di, c[3] * di);
        }
    }
    {
        int c = t >> 2, ns = (t & 3) * 32;
        int b = rowbase >> 10;
        int nb = (rowbase & 1023) + ns;
#pragma unroll 8
        for (int i = 0; i < 32; i++) {
            float v = Cs[(ns + i) * LDCX + c] * g_dinv[rowbase + ns + i];
            unsigned short hv = f2bf(v);
            size_t o = ((size_t)b * 64 + c) * NN + nb + i;
            g_dYT_hi[o] = hv;
            g_dYT_lo[o] = f2bf(v - bf2f(hv));
        }
    }
}

// ------------- K3: 2-hop reachability bitsets + zero counts -----------------
__global__ void k_adjl() {
    int warp = threadIdx.x >> 5, lane = threadIdx.x & 31;
    int row  = blockIdx.x * 8 + warp;
    int base = (row >> 10) << 10;
    unsigned myw = g_adjb[row * 32 + lane];
    unsigned acc = 0;
    for (int wk = 0; wk < 32; wk++) {
        unsigned bits = __shfl_sync(FULLM, myw, wk);
        while (bits) {
            int t = __ffs(bits) - 1; bits &= bits - 1;
            acc |= g_adjb[(size_t)(base + (wk << 5) + t) * 32 + lane];
        }
        if (__all_sync(FULLM, acc == FULLM)) break;
    }
    g_adjl[row * 32 + lane] = acc;
    int nz = __popc(~acc);
#pragma unroll
    for (int o = 16; o; o >>= 1) nz += __shfl_xor_sync(FULLM, nz, o);
    if (lane == 0) g_nz[row] = nz;
}

// ------------- helper: expand 32 adjacency bits (half row) ------------------
__device__ __forceinline__ void expand_half(__nv_bfloat16* As, int r, int hf, unsigned wrd) {
    uint4* dst = (uint4*)(As + r * LDA) + hf * 4;
#pragma unroll
    for (int seg = 0; seg < 4; seg++) {
        unsigned byte = (wrd >> (seg * 8)) & 0xFFu;
        uint4 v;
        v.x = ((byte & 1u)  ? 0x3F80u : 0u) | ((byte & 2u)   ? 0x3F800000u : 0u);
        v.y = ((byte & 4u)  ? 0x3F80u : 0u) | ((byte & 8u)   ? 0x3F800000u : 0u);
        v.z = ((byte & 16u) ? 0x3F80u : 0u) | ((byte & 32u)  ? 0x3F800000u : 0u);
        v.w = ((byte & 64u) ? 0x3F80u : 0u) | ((byte & 128u) ? 0x3F800000u : 0u);
        dst[seg] = v;
    }
}

// ------------- K4: GCN aggregate via WMMA, TM=128, 2 blocks/SM --------------
__global__ void __launch_bounds__(256, 2) k_gcn_wmma(const float* __restrict__ bg) {
    extern __shared__ char smem[];
    __nv_bfloat16* As  = (__nv_bfloat16*)smem;            // [128][LDA]
    __nv_bfloat16* Bhi = As + TMG * LDA;                  // [64][LDB]
    __nv_bfloat16* Blo = Bhi + 64 * LDB;
    float* Cs = (float*)smem;                             // alias (epilogue)

    int t = threadIdx.x, w = t >> 5;
    int wm = w & 1, wn = w >> 1;          // wm: 2x64 rows; wn: 4x16 cols
    int rowbase = blockIdx.x * TMG;
    int b = blockIdx.x >> 3;

    wmma::fragment<wmma::accumulator, 16, 16, 16, float> acc[4];
#pragma unroll
    for (int i = 0; i < 4; i++) wmma::fill_fragment(acc[i], 0.0f);

    int er = t >> 1, ehf = t & 1;
    const unsigned* arow = g_adjb + (size_t)(rowbase + er) * 32 + ehf;
    const unsigned short* ph = g_dYT_hi + (size_t)b * 64 * NN;
    const unsigned short* pl = g_dYT_lo + (size_t)b * 64 * NN;

    unsigned nw = arow[0];
    uint4 nbh[2], nbl[2];
#pragma unroll
    for (int q = 0; q < 2; q++) {
        int j = t + q * 256, c = j >> 3, seg = j & 7;
        size_t go = (size_t)c * NN + seg * 8;
        nbh[q] = *(const uint4*)(ph + go);
        nbl[q] = *(const uint4*)(pl + go);
    }

    for (int kc = 0; kc < 16; kc++) {
        unsigned wrd = nw;
        uint4 bh[2] = { nbh[0], nbh[1] }, bl[2] = { nbl[0], nbl[1] };
        __syncthreads();
        expand_half(As, er, ehf, wrd);
#pragma unroll
        for (int q = 0; q < 2; q++) {
            int j = t + q * 256, c = j >> 3, seg = j & 7;
            *(uint4*)(Bhi + c * LDB + seg * 8) = bh[q];
            *(uint4*)(Blo + c * LDB + seg * 8) = bl[q];
        }
        if (kc < 15) {
            nw = arow[(kc + 1) * 2];
#pragma unroll
            for (int q = 0; q < 2; q++) {
                int j = t + q * 256, c = j >> 3, seg = j & 7;
                size_t go = (size_t)c * NN + (kc + 1) * 64 + seg * 8;
                nbh[q] = *(const uint4*)(ph + go);
                nbl[q] = *(const uint4*)(pl + go);
            }
        }
        __syncthreads();

#pragma unroll
        for (int kt = 0; kt < 4; kt++) {
            wmma::fragment<wmma::matrix_a, 16, 16, 16, __nv_bfloat16, wmma::row_major> af[4];
#pragma unroll
            for (int i = 0; i < 4; i++)
                wmma::load_matrix_sync(af[i], As + (wm * 64 + i * 16) * LDA + kt * 16, LDA);
            wmma::fragment<wmma::matrix_b, 16, 16, 16, __nv_bfloat16, wmma::col_major> bfh, bfl;
            wmma::load_matrix_sync(bfh, Bhi + (wn * 16) * LDB + kt * 16, LDB);
            wmma::load_matrix_sync(bfl, Blo + (wn * 16) * LDB + kt * 16, LDB);
#pragma unroll
            for (int i = 0; i < 4; i++) {
                wmma::mma_sync(acc[i], af[i], bfh, acc[i]);
                wmma::mma_sync(acc[i], af[i], bfl, acc[i]);
            }
        }
    }

    __syncthreads();
#pragma unroll
    for (int i = 0; i < 4; i++)
        wmma::store_matrix_sync(Cs + (wm * 64 + i * 16) * LDC_G + wn * 16,
                                acc[i], LDC_G, wmma::mem_row_major);
    __syncthreads();

    // epilogue: h fp32 + bf16 hi/lo (row-major)
    {
        int r2 = t >> 1, half = t & 1;
        int r = rowbase + r2;
        float di = g_dinv[r];
        const float* cp = &Cs[r2 * LDC_G + half * 32];
        const float4* dyr = (const float4*)&g_dY[(size_t)r * HH + half * 32];
        float4* hr = (float4*)&g_h[(size_t)r * HH + half * 32];
        unsigned* hh = (unsigned*)&g_h_hi[(size_t)r * HH + half * 32];
        unsigned* hl = (unsigned*)&g_h_lo[(size_t)r * HH + half * 32];
#pragma unroll
        for (int i = 0; i < 8; i++) {
            float4 s = dyr[i];
            float4 bgv = *(const float4*)&bg[half * 32 + i * 4];
            float4 o;
            o.x = fmaxf(fmaf(cp[4*i+0] + s.x, di, bgv.x), 0.f);
            o.y = fmaxf(fmaf(cp[4*i+1] + s.y, di, bgv.y), 0.f);
            o.z = fmaxf(fmaf(cp[4*i+2] + s.z, di, bgv.z), 0.f);
            o.w = fmaxf(fmaf(cp[4*i+3] + s.w, di, bgv.w), 0.f);
            hr[i] = o;
            hh[i*2]   = packbf(o.x, o.y);
            hh[i*2+1] = packbf(o.z, o.w);
            hl[i*2]   = packbf(o.x - bf2f(f2bf(o.x)), o.y - bf2f(f2bf(o.y)));
            hl[i*2+1] = packbf(o.z - bf2f(f2bf(o.z)), o.w - bf2f(f2bf(o.w)));
        }
    }
}

// ------------- K5: unary + e + initial softmax ------------------------------
__global__ void k_unary_e(const float* __restrict__ Wu, const float* __restrict__ bu,
                          const float* __restrict__ means, const float* __restrict__ scales) {
    __shared__ float sW[HH * CC];
    __shared__ float sM[KK * HH], sS[KK * HH];
    for (int i = threadIdx.x; i < HH * CC; i += 256) sW[i] = Wu[i];
    for (int i = threadIdx.x; i < KK * HH; i += 256) { sM[i] = means[i]; sS[i] = scales[i]; }
    __syncthreads();
    int warp = threadIdx.x >> 5, lane = threadIdx.x & 31;
    int row  = blockIdx.x * 8 + warp;
    float h0 = g_h[(size_t)row * HH + lane];
    float h1 = g_h[(size_t)row * HH + lane + 32];
    float acc = bu[lane];
#pragma unroll
    for (int hh = 0; hh < HH; hh++) {
        float hv = __shfl_sync(FULLM, (hh < 32) ? h0 : h1, hh & 31);
        acc += hv * sW[hh * CC + lane];
    }
    g_unary[row * CC + lane] = acc;
#pragma unroll
    for (int k = 0; k < KK; k++) {
        float d0 = (h0 - sM[k * HH + lane])      / sS[k * HH + lane];
        float d1 = (h1 - sM[k * HH + lane + 32]) / sS[k * HH + lane + 32];
        float s = d0 * d0 + d1 * d1;
#pragma unroll
        for (int o = 16; o; o >>= 1) s += __shfl_xor_sync(FULLM, s, o);
        s = __shfl_sync(FULLM, s, 0);
        if (lane == 0) g_e[row * KK + k] = expf(-s);
    }
    float m = acc;
#pragma unroll
    for (int o = 16; o; o >>= 1) m = fmaxf(m, __shfl_xor_sync(FULLM, m, o));
    float ex = expf(acc - m);
    float s = ex;
#pragma unroll
    for (int o = 16; o; o >>= 1) s += __shfl_xor_sync(FULLM, s, o);
    g_Qa[row * CC + lane] = ex / s;
}

// ------------- CRF part 1: cs[k][c] = (sum_j e_jk Q_j) @ mu ------------------
__global__ void k_cs2(const float* __restrict__ mu, int sel) {
    const float* Qb = qsel(sel) + (size_t)blockIdx.x * NN * CC;
    const float* eb = g_e       + (size_t)blockIdx.x * NN * KK;
    __shared__ float ps[8][64];
    __shared__ float sMu[CC * CC];
    int t = threadIdx.x, lane = t & 31, g = t >> 5;
    for (int i = t; i < CC * CC; i += 256) sMu[i] = mu[i];
    float a0 = 0.f, a1 = 0.f;
    int j0 = g * 128;
    for (int j = j0; j < j0 + 128; j++) {
        float q = Qb[j * CC + lane];
        a0 = fmaf(eb[j * 2],     q, a0);
        a1 = fmaf(eb[j * 2 + 1], q, a1);
    }
    ps[g][lane]      = a0;
    ps[g][32 + lane] = a1;
    __syncthreads();
    if (t < 64) {
        float tv = 0.f;
#pragma unroll
        for (int w = 0; w < 8; w++) tv += ps[w][t];
        float cs = 0.f;
#pragma unroll
        for (int i = 0; i < 32; i++) {
            float ti = __shfl_sync(FULLM, tv, i);
            cs = fmaf(ti, sMu[i * 32 + lane], cs);
        }
        g_cs[blockIdx.x * 64 + t] = cs;
    }
}

// ------------- CRF part 2: msg + softmax; last iter emits QT splits ----------
__global__ void k_msg(const float* __restrict__ kw, const float* __restrict__ mu,
                      int sel, int last) {
    const float* Qin = qsel(sel);
    float* Qout = qselw(sel ^ 1);
    int warp = threadIdx.x >> 5, lane = threadIdx.x & 31;
    int row  = blockIdx.x * 8 + warp;
    int b    = row >> 10;
    int base = b << 10;
    float z0 = g_cs[b * 64 + lane], z1 = g_cs[b * 64 + 32 + lane];
    int nz = g_nz[row];
    if (__any_sync(FULLM, nz > 0)) {
        unsigned myz = ~g_adjl[row * 32 + lane];
        for (int wk = 0; wk < 32; wk++) {
            unsigned bits = __shfl_sync(FULLM, myz, wk);
            while (bits) {
                int t = __ffs(bits) - 1; bits &= bits - 1;
                int j = base + (wk << 5) + t;
                float qj = Qin[j * CC + lane];
                float p = 0.f;
#pragma unroll
                for (int c = 0; c < CC; c++)
                    p += __shfl_sync(FULLM, qj, c) * mu[c * CC + lane];
                z0 -= g_e[j * KK]     * p;
                z1 -= g_e[j * KK + 1] * p;
            }
        }
    }
    float e0 = g_e[row * KK] * kw[0], e1 = g_e[row * KK + 1] * kw[1];
    float logit = (g_unary[row * CC + lane] + e0 * z0 + e1 * z1) * INV_TEMP;
    float m = logit;
#pragma unroll
    for (int o = 16; o; o >>= 1) m = fmaxf(m, __shfl_xor_sync(FULLM, m, o));
    float ex = expf(logit - m);
    float s = ex;
#pragma unroll
    for (int o = 16; o; o >>= 1) s += __shfl_xor_sync(FULLM, s, o);
    float q = ex / s;
    Qout[row * CC + lane] = q;
    if (last) {
        int n = row & 1023;
        unsigned short hv = f2bf(q);
        size_t o = ((size_t)b * 32 + lane) * NN + n;
        g_QT_hi[o] = hv;
        g_QT_lo[o] = f2bf(q - bf2f(hv));
    }
}

// ------------- K7: AQ = adj @ Q via WMMA, TM=128; emits bf16 hi/lo ----------
__global__ void __launch_bounds__(256, 2) k_aq_wmma() {
    extern __shared__ char smem[];
    __nv_bfloat16* As  = (__nv_bfloat16*)smem;            // [128][LDA]
    __nv_bfloat16* Bhi = As + TMG * LDA;                  // [32][LDB]
    __nv_bfloat16* Blo = Bhi + 32 * LDB;
    float* Cs = (float*)smem;

    int t = threadIdx.x, w = t >> 5;
    int wm = w & 3, wn = w >> 2;          // wm: 4x32 rows; wn: 2x16 cols
    int rowbase = blockIdx.x * TMG;
    int b = blockIdx.x >> 3;

    wmma::fragment<wmma::accumulator, 16, 16, 16, float> acc[2];
#pragma unroll
    for (int i = 0; i < 2; i++) wmma::fill_fragment(acc[i], 0.0f);

    int er = t >> 1, ehf = t & 1;
    const unsigned* arow = g_adjb + (size_t)(rowbase + er) * 32 + ehf;
    const unsigned short* ph = g_QT_hi + (size_t)b * 32 * NN;
    const unsigned short* pl = g_QT_lo + (size_t)b * 32 * NN;

    unsigned nw = arow[0];
    uint4 nbh, nbl;
    {
        int c = t >> 3, seg = t & 7;
        size_t go = (size_t)c * NN + seg * 8;
        nbh = *(const uint4*)(ph + go);
        nbl = *(const uint4*)(pl + go);
    }

    for (int kc = 0; kc < 16; kc++) {
        unsigned wrd = nw;
        uint4 bh = nbh, bl = nbl;
        __syncthreads();
        expand_half(As, er, ehf, wrd);
        {
            int c = t >> 3, seg = t & 7;
            *(uint4*)(Bhi + c * LDB + seg * 8) = bh;
            *(uint4*)(Blo + c * LDB + seg * 8) = bl;
        }
        if (kc < 15) {
            nw = arow[(kc + 1) * 2];
            int c = t >> 3, seg = t & 7;
            size_t go = (size_t)c * NN + (kc + 1) * 64 + seg * 8;
            nbh = *(const uint4*)(ph + go);
            nbl = *(const uint4*)(pl + go);
        }
        __syncthreads();

#pragma unroll
        for (int kt = 0; kt < 4; kt++) {
            wmma::fragment<wmma::matrix_a, 16, 16, 16, __nv_bfloat16, wmma::row_major> af[2];
#pragma unroll
            for (int i = 0; i < 2; i++)
                wmma::load_matrix_sync(af[i], As + (wm * 32 + i * 16) * LDA + kt * 16, LDA);
            wmma::fragment<wmma::matrix_b, 16, 16, 16, __nv_bfloat16, wmma::col_major> bfh, bfl;
            wmma::load_matrix_sync(bfh, Bhi + (wn * 16) * LDB + kt * 16, LDB);
            wmma::load_matrix_sync(bfl, Blo + (wn * 16) * LDB + kt * 16, LDB);
#pragma unroll
            for (int i = 0; i < 2; i++) {
                wmma::mma_sync(acc[i], af[i], bfh, acc[i]);
                wmma::mma_sync(acc[i], af[i], bfl, acc[i]);
            }
        }
    }

    __syncthreads();
#pragma unroll
    for (int i = 0; i < 2; i++)
        wmma::store_matrix_sync(Cs + (wm * 32 + i * 16) * LDC_A + wn * 16,
                                acc[i], LDC_A, wmma::mem_row_major);
    __syncthreads();

    // epilogue: AQ bf16 hi/lo row-major [n][32]
    {
        int r2 = t >> 1, half = t & 1;
        int r = rowbase + r2;
        const float* cp = &Cs[r2 * LDC_A + half * 16];
        unsigned* ah = (unsigned*)&g_AQ_hi[(size_t)r * CC + half * 16];
        unsigned* al = (unsigned*)&g_AQ_lo[(size_t)r * CC + half * 16];
#pragma unroll
        for (int i = 0; i < 8; i++) {
            float v0 = cp[2*i], v1 = cp[2*i+1];
            ah[i] = packbf(v0, v1);
            al[i] = packbf(v0 - bf2f(f2bf(v0)), v1 - bf2f(f2bf(v1)));
        }
    }
}

// ------------- K8: pooled outputs via WMMA (Q^T@h | Q^T@AQ) -----------------
__global__ void __launch_bounds__(256, 1) k_pool_wmma(float* __restrict__ out) {
    extern __shared__ float sp[];                    // [8][32][LDP]
    int b = blockIdx.x, t = threadIdx.x, w = t >> 5;

    const __nv_bfloat16* qh = (const __nv_bfloat16*)(g_QT_hi + (size_t)b * 32 * NN);
    const __nv_bfloat16* ql = (const __nv_bfloat16*)(g_QT_lo + (size_t)b * 32 * NN);

    wmma::fragment<wmma::accumulator, 16, 16, 16, float> acc[2][6];
#pragma unroll
    for (int i = 0; i < 2; i++)
#pragma unroll
        for (int j = 0; j < 6; j++) wmma::fill_fragment(acc[i][j], 0.0f);

    for (int kk = 0; kk < 8; kk++) {
        int k = w * 128 + kk * 16;
        wmma::fragment<wmma::matrix_a, 16, 16, 16, __nv_bfloat16, wmma::row_major> ah[2], al[2];
#pragma unroll
        for (int mi = 0; mi < 2; mi++) {
            wmma::load_matrix_sync(ah[mi], qh + (mi * 16) * NN + k, NN);
            wmma::load_matrix_sync(al[mi], ql + (mi * 16) * NN + k, NN);
        }
#pragma unroll
        for (int j = 0; j < 6; j++) {
            const __nv_bfloat16 *bhp, *blp; unsigned ldb_;
            if (j < 4) {
                size_t o = ((size_t)(b * NN + k)) * HH + j * 16;
                bhp = (const __nv_bfloat16*)(g_h_hi + o);
                blp = (const __nv_bfloat16*)(g_h_lo + o);
                ldb_ = HH;
            } else {
                size_t o = ((size_t)(b * NN + k)) * CC + (j - 4) * 16;
                bhp = (const __nv_bfloat16*)(g_AQ_hi + o);
                blp = (const __nv_bfloat16*)(g_AQ_lo + o);
                ldb_ = CC;
            }
            wmma::fragment<wmma::matrix_b, 16, 16, 16, __nv_bfloat16, wmma::row_major> bh, bl;
            wmma::load_matrix_sync(bh, bhp, ldb_);
            wmma::load_matrix_sync(bl, blp, ldb_);
#pragma unroll
            for (int mi = 0; mi < 2; mi++) {
                wmma::mma_sync(acc[mi][j], ah[mi], bh, acc[mi][j]);
                wmma::mma_sync(acc[mi][j], ah[mi], bl, acc[mi][j]);
                wmma::mma_sync(acc[mi][j], al[mi], bh, acc[mi][j]);
            }
        }
    }

    float* wbase = sp + w * 32 * LDP;
#pragma unroll
    for (int mi = 0; mi < 2; mi++)
#pragma unroll
        for (int j = 0; j < 6; j++)
            wmma::store_matrix_sync(wbase + (mi * 16) * LDP + j * 16,
                                    acc[mi][j], LDP, wmma::mem_row_major);
    __syncthreads();

#pragma unroll
    for (int i = 0; i < 12; i++) {
        int oi = i * 256 + t;
        int c = oi / 96, col = oi - c * 96;
        float s = 0.f;
#pragma unroll
        for (int w8 = 0; w8 < 8; w8++) s += sp[w8 * 32 * LDP + c * LDP + col];
        if (col < 64)
            out[((size_t)b * CC + c) * HH + col] = s;
        else
            out[(size_t)BB * CC * HH + ((size_t)b * CC + c) * CC + (col - 64)] = s;
    }
}

// ---------------------------------------------------------------------------
extern "C" void kernel_launch(void* const* d_in, const int* in_sizes, int n_in,
                              void* d_out, int out_size) {
    const float* x      = (const float*)d_in[0];
    const int*   adj    = (const int*)  d_in[1];
    const float* Wg     = (const float*)d_in[2];
    const float* bg     = (const float*)d_in[3];
    const float* Wu     = (const float*)d_in[4];
    const float* bu     = (const float*)d_in[5];
    const float* means  = (const float*)d_in[6];
    const float* scales = (const float*)d_in[7];
    const float* kw     = (const float*)d_in[8];
    const float* mu     = (const float*)d_in[9];
    float* out = (float*)d_out;

    cudaFuncSetAttribute(k_xw_wmma,   cudaFuncAttributeMaxDynamicSharedMemorySize, SMEM_X);
    cudaFuncSetAttribute(k_gcn_wmma,  cudaFuncAttributeMaxDynamicSharedMemorySize, SMEM_G2);
    cudaFuncSetAttribute(k_aq_wmma,   cudaFuncAttributeMaxDynamicSharedMemorySize, SMEM_A2);
    cudaFuncSetAttribute(k_pool_wmma, cudaFuncAttributeMaxDynamicSharedMemorySize, SMEM_P);

    k_bits     <<<ROWS / 8,   256>>>(adj);
    k_xw_wmma  <<<ROWS / TMX, 256, SMEM_X>>>(x, Wg);
    k_adjl     <<<ROWS / 8,   256>>>();
    k_gcn_wmma <<<ROWS / TMG, 256, SMEM_G2>>>(bg);
    k_unary_e  <<<ROWS / 8,   256>>>(Wu, bu, means, scales);

    int sel = 0;
    for (int it = 0; it < NITER; it++) {
        k_cs2 <<<BB,       256>>>(mu, sel);
        k_msg <<<ROWS / 8, 256>>>(kw, mu, sel, it == NITER - 1);
        sel ^= 1;
    }

    k_aq_wmma   <<<ROWS / TMG, 256, SMEM_A2>>>();
    k_pool_wmma <<<BB, 256, SMEM_P>>>(out);
}

// round 14
// speedup vs baseline: 1.0554x; 1.0554x over previous
#include <cuda_runtime.h>
#include <cuda_bf16.h>
#include <mma.h>

using namespace nvcuda;

#define BB 32
#define NN 1024
#define FF 128
#define HH 64
#define CC 32
#define KK 2
#define NITER 5
#define INV_TEMP 2.0f
#define ROWS (BB*NN)
#define FULLM 0xffffffffu

// WMMA tiling (family-portable HMMA; round-12 proven shapes)
#define TM 256          // rows per block (gcn/aq)
#define LDA 72          // bf16 elems
#define LDB 72
#define LDC_G 72        // f32 elems
#define LDC_A 40
#define SMEM_WG (TM*LDC_G*4)                 // 73728 (Cs alias dominates)
#define SMEM_WA ((TM*LDA + 2*32*LDB) * 2)    // 46080

// k_xw WMMA tiling
#define TMX 128
#define LDX 136
#define LDW 72
#define LDCX 72
#define SMEM_X ((2*TMX*LDX + 2*FF*LDW) * 2)  // 106496

__device__ __forceinline__ unsigned short f2bf(float f) {
    return __bfloat16_as_ushort(__float2bfloat16(f));
}
__device__ __forceinline__ float bf2f(unsigned short u) {
    return __bfloat162float(__ushort_as_bfloat16(u));
}

// ---------------- scratch (device globals; allocation-free) ----------------
__device__ float          g_dY[ROWS*HH];
__device__ float          g_dinv[ROWS];
__device__ unsigned       g_adjb[ROWS*32];
__device__ unsigned       g_adjl[ROWS*32];
__device__ int            g_nz[ROWS];
__device__ float          g_h[ROWS*HH];
__device__ float          g_unary[ROWS*CC];
__device__ float          g_e[ROWS*KK];
__device__ float          g_Qa[ROWS*CC];
__device__ float          g_Qb[ROWS*CC];
__device__ float          g_csp[(ROWS/8)*64];   // per-block e-weighted Q colsum partials
__device__ float          g_cs[BB*64];
__device__ float          g_AQ[ROWS*CC];
__device__ float          g_poolp[(size_t)BB*16*3072];
__device__ unsigned short g_dYT_hi[(size_t)BB*64*NN];   // [b][c][n] bf16
__device__ unsigned short g_dYT_lo[(size_t)BB*64*NN];
__device__ unsigned short g_QT_hi[(size_t)BB*32*NN];
__device__ unsigned short g_QT_lo[(size_t)BB*32*NN];

__device__ __forceinline__ const float* qsel(int s) { return s ? g_Qb : g_Qa; }
__device__ __forceinline__ float*       qselw(int s){ return s ? g_Qb : g_Qa; }

// ------------- K1: pack adjacency bits + degree -> dinv ---------------------
__global__ void k_bits(const int* __restrict__ adj) {
    int warp = threadIdx.x >> 5, lane = threadIdx.x & 31;
    int row  = blockIdx.x * 8 + warp;
    const int* ar = adj + (size_t)row * NN;
    unsigned myw = 0;
#pragma unroll
    for (int w = 0; w < 32; w++) {
        unsigned bal = __ballot_sync(FULLM, ar[(w << 5) + lane] != 0);
        if (lane == w) myw = bal;
    }
    g_adjb[row * 32 + lane] = myw;
    int d = __popc(myw);
#pragma unroll
    for (int o = 16; o; o >>= 1) d += __shfl_xor_sync(FULLM, d, o);
    if (lane == 0) g_dinv[row] = rsqrtf((float)d + 1.0f);
}

// ------------- K2: dY = (x @ W_gcn)*dinv via WMMA (hi/lo split both) --------
__global__ void __launch_bounds__(256, 1) k_xw_wmma(const float* __restrict__ x,
                                                    const float* __restrict__ Wg) {
    extern __shared__ char smem[];
    __nv_bfloat16* Ah = (__nv_bfloat16*)smem;      // [TMX][LDX]
    __nv_bfloat16* Al = Ah + TMX * LDX;
    __nv_bfloat16* Bh = Al + TMX * LDX;            // [FF][LDW]
    __nv_bfloat16* Bl = Bh + FF * LDW;
    float* Cs = (float*)smem;                      // alias (epilogue)

    int t = threadIdx.x, w = t >> 5;
    int rowbase = blockIdx.x * TMX;

    for (int i = t; i < FF * HH; i += 256) {
        float v = Wg[i];
        unsigned short hv = f2bf(v);
        int r = i >> 6, c = i & 63;
        Bh[r * LDW + c] = __ushort_as_bfloat16(hv);
        Bl[r * LDW + c] = __ushort_as_bfloat16(f2bf(v - bf2f(hv)));
    }
    {
        const float4* xs = (const float4*)(x + (size_t)rowbase * FF);
        for (int i = t; i < TMX * FF / 4; i += 256) {
            float4 v = xs[i];
            int r = i >> 5, c4 = (i & 31) * 4;
            unsigned short h0 = f2bf(v.x), h1 = f2bf(v.y), h2 = f2bf(v.z), h3 = f2bf(v.w);
            __nv_bfloat16* ah = Ah + r * LDX + c4;
            __nv_bfloat16* al = Al + r * LDX + c4;
            ah[0] = __ushort_as_bfloat16(h0); al[0] = __ushort_as_bfloat16(f2bf(v.x - bf2f(h0)));
            ah[1] = __ushort_as_bfloat16(h1); al[1] = __ushort_as_bfloat16(f2bf(v.y - bf2f(h1)));
            ah[2] = __ushort_as_bfloat16(h2); al[2] = __ushort_as_bfloat16(f2bf(v.z - bf2f(h2)));
            ah[3] = __ushort_as_bfloat16(h3); al[3] = __ushort_as_bfloat16(f2bf(v.w - bf2f(h3)));
        }
    }
    __syncthreads();

    wmma::fragment<wmma::accumulator, 16, 16, 16, float> acc[4];
#pragma unroll
    for (int j = 0; j < 4; j++) wmma::fill_fragment(acc[j], 0.0f);
#pragma unroll
    for (int kt = 0; kt < 8; kt++) {
        wmma::fragment<wmma::matrix_a, 16, 16, 16, __nv_bfloat16, wmma::row_major> ah, al;
        wmma::load_matrix_sync(ah, Ah + (w * 16) * LDX + kt * 16, LDX);
        wmma::load_matrix_sync(al, Al + (w * 16) * LDX + kt * 16, LDX);
#pragma unroll
        for (int j = 0; j < 4; j++) {
            wmma::fragment<wmma::matrix_b, 16, 16, 16, __nv_bfloat16, wmma::row_major> bh, bl;
            wmma::load_matrix_sync(bh, Bh + kt * 16 * LDW + j * 16, LDW);
            wmma::load_matrix_sync(bl, Bl + kt * 16 * LDW + j * 16, LDW);
            wmma::mma_sync(acc[j], ah, bh, acc[j]);
            wmma::mma_sync(acc[j], ah, bl, acc[j]);
            wmma::mma_sync(acc[j], al, bh, acc[j]);
        }
    }
    __syncthreads();
#pragma unroll
    for (int j = 0; j < 4; j++)
        wmma::store_matrix_sync(Cs + (w * 16) * LDCX + j * 16, acc[j], LDCX, wmma::mem_row_major);
    __syncthreads();

    {
        int r2 = t >> 1, half = t & 1;
        int grow = rowbase + r2;
        float di = g_dinv[grow];
        float4* dst = (float4*)&g_dY[(size_t)grow * HH + half * 32];
#pragma unroll
        for (int i = 0; i < 8; i++) {
            const float* c = &Cs[r2 * LDCX + half * 32 + i * 4];
            dst[i] = make_float4(c[0] * di, c[1] * di, c[2] * di, c[3] * di);
        }
    }
    {
        int c = t >> 2, ns = (t & 3) * 32;
        int b = rowbase >> 10;
        int nb = (rowbase & 1023) + ns;
#pragma unroll 8
        for (int i = 0; i < 32; i++) {
            float v = Cs[(ns + i) * LDCX + c] * g_dinv[rowbase + ns + i];
            unsigned short hv = f2bf(v);
            size_t o = ((size_t)b * 64 + c) * NN + nb + i;
            g_dYT_hi[o] = hv;
            g_dYT_lo[o] = f2bf(v - bf2f(hv));
        }
    }
}

// ------------- K3: 2-hop reachability bitsets + zero counts -----------------
__global__ void k_adjl() {
    int warp = threadIdx.x >> 5, lane = threadIdx.x & 31;
    int row  = blockIdx.x * 8 + warp;
    int base = (row >> 10) << 10;
    unsigned myw = g_adjb[row * 32 + lane];
    unsigned acc = 0;
    for (int wk = 0; wk < 32; wk++) {
        unsigned bits = __shfl_sync(FULLM, myw, wk);
        while (bits) {
            int t = __ffs(bits) - 1; bits &= bits - 1;
            acc |= g_adjb[(size_t)(base + (wk << 5) + t) * 32 + lane];
        }
        if (__all_sync(FULLM, acc == FULLM)) break;
    }
    g_adjl[row * 32 + lane] = acc;
    int nz = __popc(~acc);
#pragma unroll
    for (int o = 16; o; o >>= 1) nz += __shfl_xor_sync(FULLM, nz, o);
    if (lane == 0) g_nz[row] = nz;
}

// ------------- helper: expand 64 adjacency bits into a bf16 smem row --------
__device__ __forceinline__ void expand_row(__nv_bfloat16* As, int t, unsigned w0, unsigned w1) {
    uint4* dst = (uint4*)(As + t * LDA);
#pragma unroll
    for (int seg = 0; seg < 8; seg++) {
        unsigned byte = ((seg < 4) ? (w0 >> (seg * 8)) : (w1 >> ((seg - 4) * 8))) & 0xFFu;
        uint4 v;
        v.x = ((byte & 1u)  ? 0x3F80u : 0u) | ((byte & 2u)   ? 0x3F800000u : 0u);
        v.y = ((byte & 4u)  ? 0x3F80u : 0u) | ((byte & 8u)   ? 0x3F800000u : 0u);
        v.z = ((byte & 16u) ? 0x3F80u : 0u) | ((byte & 32u)  ? 0x3F800000u : 0u);
        v.w = ((byte & 64u) ? 0x3F80u : 0u) | ((byte & 128u) ? 0x3F800000u : 0u);
        dst[seg] = v;
    }
}

// ------------- K4: GCN aggregate via WMMA bf16 hi+lo split (round-12) -------
__global__ void __launch_bounds__(256, 1) k_gcn_wmma(const float* __restrict__ bg) {
    extern __shared__ char smem[];
    __nv_bfloat16* As  = (__nv_bfloat16*)smem;            // [256][LDA]
    __nv_bfloat16* Bhi = As + TM * LDA;                   // [64][LDB]
    __nv_bfloat16* Blo = Bhi + 64 * LDB;
    float* Cs = (float*)smem;                             // alias (epilogue)

    int t = threadIdx.x, w = t >> 5;
    int wm = w & 3, wn = w >> 2;
    int rowbase = blockIdx.x * TM;
    int b = blockIdx.x >> 2;

    wmma::fragment<wmma::accumulator, 16, 16, 16, float> acc[4][2];
#pragma unroll
    for (int i = 0; i < 4; i++)
#pragma unroll
        for (int j = 0; j < 2; j++) wmma::fill_fragment(acc[i][j], 0.0f);

    const unsigned* arow = g_adjb + (size_t)(rowbase + t) * 32;
    const unsigned short* ph = g_dYT_hi + (size_t)b * 64 * NN;
    const unsigned short* pl = g_dYT_lo + (size_t)b * 64 * NN;

    unsigned nw0 = arow[0], nw1 = arow[1];
    uint4 nbh[2], nbl[2];
#pragma unroll
    for (int q = 0; q < 2; q++) {
        int j = t + q * 256, c = j >> 3, seg = j & 7;
        size_t go = (size_t)c * NN + seg * 8;
        nbh[q] = *(const uint4*)(ph + go);
        nbl[q] = *(const uint4*)(pl + go);
    }

    for (int kc = 0; kc < 16; kc++) {
        unsigned w0 = nw0, w1 = nw1;
        uint4 bh[2] = { nbh[0], nbh[1] }, bl[2] = { nbl[0], nbl[1] };
        __syncthreads();
        expand_row(As, t, w0, w1);
#pragma unroll
        for (int q = 0; q < 2; q++) {
            int j = t + q * 256, c = j >> 3, seg = j & 7;
            *(uint4*)(Bhi + c * LDB + seg * 8) = bh[q];
            *(uint4*)(Blo + c * LDB + seg * 8) = bl[q];
        }
        if (kc < 15) {
            nw0 = arow[(kc + 1) * 2];
            nw1 = arow[(kc + 1) * 2 + 1];
#pragma unroll
            for (int q = 0; q < 2; q++) {
                int j = t + q * 256, c = j >> 3, seg = j & 7;
                size_t go = (size_t)c * NN + (kc + 1) * 64 + seg * 8;
                nbh[q] = *(const uint4*)(ph + go);
                nbl[q] = *(const uint4*)(pl + go);
            }
        }
        __syncthreads();

#pragma unroll
        for (int kt = 0; kt < 4; kt++) {
            wmma::fragment<wmma::matrix_a, 16, 16, 16, __nv_bfloat16, wmma::row_major> af[4];
#pragma unroll
            for (int i = 0; i < 4; i++)
                wmma::load_matrix_sync(af[i], As + (wm * 64 + i * 16) * LDA + kt * 16, LDA);
#pragma unroll
            for (int j = 0; j < 2; j++) {
                wmma::fragment<wmma::matrix_b, 16, 16, 16, __nv_bfloat16, wmma::col_major> bfh, bfl;
                wmma::load_matrix_sync(bfh, Bhi + (wn * 32 + j * 16) * LDB + kt * 16, LDB);
                wmma::load_matrix_sync(bfl, Blo + (wn * 32 + j * 16) * LDB + kt * 16, LDB);
#pragma unroll
                for (int i = 0; i < 4; i++) {
                    wmma::mma_sync(acc[i][j], af[i], bfh, acc[i][j]);
                    wmma::mma_sync(acc[i][j], af[i], bfl, acc[i][j]);
                }
            }
        }
    }

    __syncthreads();
#pragma unroll
    for (int i = 0; i < 4; i++)
#pragma unroll
        for (int j = 0; j < 2; j++)
            wmma::store_matrix_sync(Cs + (wm * 64 + i * 16) * LDC_G + (wn * 32 + j * 16),
                                    acc[i][j], LDC_G, wmma::mem_row_major);
    __syncthreads();

    int r = rowbase + t;
    float di = g_dinv[r];
    const float4* dyr = (const float4*)&g_dY[(size_t)r * HH];
    float4* hr = (float4*)&g_h[(size_t)r * HH];
#pragma unroll
    for (int i = 0; i < 16; i++) {
        float4 s = dyr[i];
        float4 o;
        o.x = fmaxf(fmaf(Cs[t * LDC_G + 4*i+0] + s.x, di, bg[4*i+0]), 0.f);
        o.y = fmaxf(fmaf(Cs[t * LDC_G + 4*i+1] + s.y, di, bg[4*i+1]), 0.f);
        o.z = fmaxf(fmaf(Cs[t * LDC_G + 4*i+2] + s.z, di, bg[4*i+2]), 0.f);
        o.w = fmaxf(fmaf(Cs[t * LDC_G + 4*i+3] + s.w, di, bg[4*i+3]), 0.f);
        hr[i] = o;
    }
}

// ------------- K5: unary + e + initial softmax + colsum partials ------------
__global__ void k_unary_e(const float* __restrict__ Wu, const float* __restrict__ bu,
                          const float* __restrict__ means, const float* __restrict__ scales) {
    __shared__ float sW[HH * CC];
    __shared__ float sM[KK * HH], sS[KK * HH];
    __shared__ float sp[8][64];
    for (int i = threadIdx.x; i < HH * CC; i += 256) sW[i] = Wu[i];
    for (int i = threadIdx.x; i < KK * HH; i += 256) { sM[i] = means[i]; sS[i] = scales[i]; }
    __syncthreads();
    int warp = threadIdx.x >> 5, lane = threadIdx.x & 31;
    int row  = blockIdx.x * 8 + warp;
    float h0 = g_h[(size_t)row * HH + lane];
    float h1 = g_h[(size_t)row * HH + lane + 32];
    float acc = bu[lane];
#pragma unroll
    for (int hh = 0; hh < HH; hh++) {
        float hv = __shfl_sync(FULLM, (hh < 32) ? h0 : h1, hh & 31);
        acc += hv * sW[hh * CC + lane];
    }
    g_unary[row * CC + lane] = acc;
    float ek[2];
#pragma unroll
    for (int k = 0; k < KK; k++) {
        float d0 = (h0 - sM[k * HH + lane])      / sS[k * HH + lane];
        float d1 = (h1 - sM[k * HH + lane + 32]) / sS[k * HH + lane + 32];
        float s = d0 * d0 + d1 * d1;
#pragma unroll
        for (int o = 16; o; o >>= 1) s += __shfl_xor_sync(FULLM, s, o);
        s = __shfl_sync(FULLM, s, 0);
        ek[k] = expf(-s);
        if (lane == 0) g_e[row * KK + k] = ek[k];
    }
    float m = acc;
#pragma unroll
    for (int o = 16; o; o >>= 1) m = fmaxf(m, __shfl_xor_sync(FULLM, m, o));
    float ex = expf(acc - m);
    float s = ex;
#pragma unroll
    for (int o = 16; o; o >>= 1) s += __shfl_xor_sync(FULLM, s, o);
    float q = ex / s;
    g_Qa[row * CC + lane] = q;
    sp[warp][lane]      = ek[0] * q;
    sp[warp][32 + lane] = ek[1] * q;
    __syncthreads();
    int t = threadIdx.x;
    if (t < 64) {
        float v = 0.f;
#pragma unroll
        for (int w = 0; w < 8; w++) v += sp[w][t];
        g_csp[blockIdx.x * 64 + t] = v;
    }
}

// ------------- CRF reduce: cs[k][c] = (sum partials) @ mu --------------------
__global__ void k_csr(const float* __restrict__ mu) {
    __shared__ float sMu[CC * CC];
    int b = blockIdx.x, t = threadIdx.x, lane = t & 31;   // 64 threads
    for (int i = t; i < CC * CC; i += 64) sMu[i] = mu[i];
    __syncthreads();
    float tv = 0.f;
    for (int i = 0; i < 128; i++) tv += g_csp[(b * 128 + i) * 64 + t];
    float cs = 0.f;
#pragma unroll
    for (int i = 0; i < 32; i++) {
        float ti = __shfl_sync(FULLM, tv, i);
        cs = fmaf(ti, sMu[i * 32 + lane], cs);
    }
    g_cs[b * 64 + t] = cs;
}

// ------------- CRF msg + softmax + colsum partials; last emits QT -----------
__global__ void k_msg(const float* __restrict__ kw, const float* __restrict__ mu,
                      int sel, int last) {
    const float* Qin = qsel(sel);
    float* Qout = qselw(sel ^ 1);
    __shared__ float sp[8][64];
    int warp = threadIdx.x >> 5, lane = threadIdx.x & 31;
    int row  = blockIdx.x * 8 + warp;
    int b    = row >> 10;
    int base = b << 10;
    float z0 = g_cs[b * 64 + lane], z1 = g_cs[b * 64 + 32 + lane];
    int nz = g_nz[row];
    if (__any_sync(FULLM, nz > 0)) {
        unsigned myz = ~g_adjl[row * 32 + lane];
        for (int wk = 0; wk < 32; wk++) {
            unsigned bits = __shfl_sync(FULLM, myz, wk);
            while (bits) {
                int t = __ffs(bits) - 1; bits &= bits - 1;
                int j = base + (wk << 5) + t;
                float qj = Qin[j * CC + lane];
                float p = 0.f;
#pragma unroll
                for (int c = 0; c < CC; c++)
                    p += __shfl_sync(FULLM, qj, c) * mu[c * CC + lane];
                z0 -= g_e[j * KK]     * p;
                z1 -= g_e[j * KK + 1] * p;
            }
        }
    }
    float e0r = g_e[row * KK], e1r = g_e[row * KK + 1];
    float logit = (g_unary[row * CC + lane] + e0r * kw[0] * z0 + e1r * kw[1] * z1) * INV_TEMP;
    float m = logit;
#pragma unroll
    for (int o = 16; o; o >>= 1) m = fmaxf(m, __shfl_xor_sync(FULLM, m, o));
    float ex = expf(logit - m);
    float s = ex;
#pragma unroll
    for (int o = 16; o; o >>= 1) s += __shfl_xor_sync(FULLM, s, o);
    float q = ex / s;
    Qout[row * CC + lane] = q;
    if (last) {
        int n = row & 1023;
        unsigned short hv = f2bf(q);
        size_t o = ((size_t)b * 32 + lane) * NN + n;
        g_QT_hi[o] = hv;
        g_QT_lo[o] = f2bf(q - bf2f(hv));
    } else {
        sp[warp][lane]      = e0r * q;
        sp[warp][32 + lane] = e1r * q;
        __syncthreads();
        int t = threadIdx.x;
        if (t < 64) {
            float v = 0.f;
#pragma unroll
            for (int w = 0; w < 8; w++) v += sp[w][t];
            g_csp[blockIdx.x * 64 + t] = v;
        }
    }
}

// ------------- K7: AQ = adj @ Q via WMMA bf16 hi+lo split (round-12) --------
__global__ void __launch_bounds__(256, 1) k_aq_wmma() {
    extern __shared__ char smem[];
    __nv_bfloat16* As  = (__nv_bfloat16*)smem;            // [256][LDA]
    __nv_bfloat16* Bhi = As + TM * LDA;                   // [32][LDB]
    __nv_bfloat16* Blo = Bhi + 32 * LDB;
    float* Cs = (float*)smem;

    int t = threadIdx.x, w = t >> 5;
    int wm = w & 3, wn = w >> 2;
    int rowbase = blockIdx.x * TM;
    int b = blockIdx.x >> 2;

    wmma::fragment<wmma::accumulator, 16, 16, 16, float> acc[4];
#pragma unroll
    for (int i = 0; i < 4; i++) wmma::fill_fragment(acc[i], 0.0f);

    const unsigned* arow = g_adjb + (size_t)(rowbase + t) * 32;
    const unsigned short* ph = g_QT_hi + (size_t)b * 32 * NN;
    const unsigned short* pl = g_QT_lo + (size_t)b * 32 * NN;

    unsigned nw0 = arow[0], nw1 = arow[1];
    uint4 nbh, nbl;
    {
        int c = t >> 3, seg = t & 7;
        size_t go = (size_t)c * NN + seg * 8;
        nbh = *(const uint4*)(ph + go);
        nbl = *(const uint4*)(pl + go);
    }

    for (int kc = 0; kc < 16; kc++) {
        unsigned w0 = nw0, w1 = nw1;
        uint4 bh = nbh, bl = nbl;
        __syncthreads();
        expand_row(As, t, w0, w1);
        {
            int c = t >> 3, seg = t & 7;
            *(uint4*)(Bhi + c * LDB + seg * 8) = bh;
            *(uint4*)(Blo + c * LDB + seg * 8) = bl;
        }
        if (kc < 15) {
            nw0 = arow[(kc + 1) * 2];
            nw1 = arow[(kc + 1) * 2 + 1];
            int c = t >> 3, seg = t & 7;
            size_t go = (size_t)c * NN + (kc + 1) * 64 + seg * 8;
            nbh = *(const uint4*)(ph + go);
            nbl = *(const uint4*)(pl + go);
        }
        __syncthreads();

#pragma unroll
        for (int kt = 0; kt < 4; kt++) {
            wmma::fragment<wmma::matrix_a, 16, 16, 16, __nv_bfloat16, wmma::row_major> af[4];
#pragma unroll
            for (int i = 0; i < 4; i++)
                wmma::load_matrix_sync(af[i], As + (wm * 64 + i * 16) * LDA + kt * 16, LDA);
            wmma::fragment<wmma::matrix_b, 16, 16, 16, __nv_bfloat16, wmma::col_major> bfh, bfl;
            wmma::load_matrix_sync(bfh, Bhi + (wn * 16) * LDB + kt * 16, LDB);
            wmma::load_matrix_sync(bfl, Blo + (wn * 16) * LDB + kt * 16, LDB);
#pragma unroll
            for (int i = 0; i < 4; i++) {
                wmma::mma_sync(acc[i], af[i], bfh, acc[i]);
                wmma::mma_sync(acc[i], af[i], bfl, acc[i]);
            }
        }
    }

    __syncthreads();
#pragma unroll
    for (int i = 0; i < 4; i++)
        wmma::store_matrix_sync(Cs + (wm * 64 + i * 16) * LDC_A + wn * 16,
                                acc[i], LDC_A, wmma::mem_row_major);
    __syncthreads();

    int r = rowbase + t;
    float4* ar = (float4*)&g_AQ[(size_t)r * CC];
#pragma unroll
    for (int i = 0; i < 8; i++)
        ar[i] = make_float4(Cs[t * LDC_A + 4*i+0], Cs[t * LDC_A + 4*i+1],
                            Cs[t * LDC_A + 4*i+2], Cs[t * LDC_A + 4*i+3]);
}

// ------------- K8a: pooled outputs, N-split partials ------------------------
__global__ void k_poolp(int sel) {
    const float* Qf = qsel(sel);
    __shared__ float Qs[64 * 32];
    __shared__ float hs[64 * 64];
    __shared__ float Aq[64 * 32];
    int b = blockIdx.x, nc = blockIdx.y;
    int tid = threadIdx.x;
    int n0 = b * NN + nc * 64;
    {
        const float4* sq = (const float4*)(Qf   + (size_t)n0 * CC);
        const float4* sh = (const float4*)(g_h  + (size_t)n0 * HH);
        const float4* sa = (const float4*)(g_AQ + (size_t)n0 * CC);
        ((float4*)Qs)[tid] = sq[tid];  ((float4*)Qs)[tid + 256] = sq[tid + 256];
        ((float4*)Aq)[tid] = sa[tid];  ((float4*)Aq)[tid + 256] = sa[tid + 256];
#pragma unroll
        for (int q = 0; q < 4; q++) ((float4*)hs)[tid + q * 256] = sh[tid + q * 256];
    }
    __syncthreads();
    int tx = tid & 15, ty = tid >> 4;
    float xp[2][4] = {};
    float ap[2][2] = {};
    for (int n = 0; n < 64; n++) {
        float q0 = Qs[n * 32 + ty * 2], q1 = Qs[n * 32 + ty * 2 + 1];
        float4 hv = *(const float4*)&hs[n * 64 + tx * 4];
        float a0 = Aq[n * 32 + tx * 2], a1 = Aq[n * 32 + tx * 2 + 1];
        xp[0][0] += q0 * hv.x; xp[0][1] += q0 * hv.y; xp[0][2] += q0 * hv.z; xp[0][3] += q0 * hv.w;
        xp[1][0] += q1 * hv.x; xp[1][1] += q1 * hv.y; xp[1][2] += q1 * hv.z; xp[1][3] += q1 * hv.w;
        ap[0][0] += q0 * a0; ap[0][1] += q0 * a1;
        ap[1][0] += q1 * a0; ap[1][1] += q1 * a1;
    }
    float* dst = g_poolp + ((size_t)b * 16 + nc) * 3072;
#pragma unroll
    for (int cc = 0; cc < 2; cc++) {
#pragma unroll
        for (int c4 = 0; c4 < 4; c4++)
            dst[(ty * 2 + cc) * 64 + tx * 4 + c4] = xp[cc][c4];
#pragma unroll
        for (int a = 0; a < 2; a++)
            dst[2048 + (ty * 2 + cc) * 32 + tx * 2 + a] = ap[cc][a];
    }
}

// ------------- K8b: reduce pooling partials ---------------------------------
__global__ void k_poolred(float* __restrict__ out) {
    int b = blockIdx.x;
    int idx = blockIdx.y * 256 + threadIdx.x;
    float s = 0.f;
    for (int ch = 0; ch < 16; ch++) s += g_poolp[((size_t)b * 16 + ch) * 3072 + idx];
    if (idx < 2048) {
        int c = idx >> 6, hcol = idx & 63;
        out[((size_t)b * CC + c) * HH + hcol] = s;
    } else {
        int j = idx - 2048, c = j >> 5, a = j & 31;
        out[(size_t)BB * CC * HH + ((size_t)b * CC + c) * CC + a] = s;
    }
}

// ---------------------------------------------------------------------------
extern "C" void kernel_launch(void* const* d_in, const int* in_sizes, int n_in,
                              void* d_out, int out_size) {
    const float* x      = (const float*)d_in[0];
    const int*   adj    = (const int*)  d_in[1];
    const float* Wg     = (const float*)d_in[2];
    const float* bg     = (const float*)d_in[3];
    const float* Wu     = (const float*)d_in[4];
    const float* bu     = (const float*)d_in[5];
    const float* means  = (const float*)d_in[6];
    const float* scales = (const float*)d_in[7];
    const float* kw     = (const float*)d_in[8];
    const float* mu     = (const float*)d_in[9];
    float* out = (float*)d_out;

    cudaFuncSetAttribute(k_xw_wmma,  cudaFuncAttributeMaxDynamicSharedMemorySize, SMEM_X);
    cudaFuncSetAttribute(k_gcn_wmma, cudaFuncAttributeMaxDynamicSharedMemorySize, SMEM_WG);
    cudaFuncSetAttribute(k_aq_wmma,  cudaFuncAttributeMaxDynamicSharedMemorySize, SMEM_WA);

    k_bits     <<<ROWS / 8,   256>>>(adj);
    k_xw_wmma  <<<ROWS / TMX, 256, SMEM_X>>>(x, Wg);
    k_adjl     <<<ROWS / 8,   256>>>();
    k_gcn_wmma <<<ROWS / TM,  256, SMEM_WG>>>(bg);
    k_unary_e  <<<ROWS / 8,   256>>>(Wu, bu, means, scales);

    int sel = 0;
    for (int it = 0; it < NITER; it++) {
        k_csr <<<BB,       64>>>(mu);
        k_msg <<<ROWS / 8, 256>>>(kw, mu, sel, it == NITER - 1);
        sel ^= 1;
    }

    k_aq_wmma <<<ROWS / TM, 256, SMEM_WA>>>();
    k_poolp   <<<dim3(BB, 16), 256>>>(sel);
    k_poolred <<<dim3(BB, 12), 256>>>(out);
}

// round 15
// speedup vs baseline: 1.0847x; 1.0277x over previous
#include <cuda_runtime.h>
#include <cuda_bf16.h>
#include <mma.h>

using namespace nvcuda;

#define BB 32
#define NN 1024
#define FF 128
#define HH 64
#define CC 32
#define KK 2
#define NITER 5
#define INV_TEMP 2.0f
#define ROWS (BB*NN)
#define FULLM 0xffffffffu

// WMMA tiling (family-portable HMMA; proven shapes)
#define TM 256          // rows per block (gcn/aq)
#define LDA 72          // bf16 elems
#define LDB 72
#define LDC_G 72        // f32 elems
#define LDC_A 40
#define SMEM_WG (TM*LDC_G*4)                 // 73728 (Cs alias dominates)
#define SMEM_WA ((TM*LDA + 2*32*LDB) * 2)    // 46080

// k_xw WMMA tiling
#define TMX 128
#define LDX 136
#define LDW 72
#define LDCX 72
#define SMEM_X ((2*TMX*LDX + 2*FF*LDW) * 2)  // 106496

// pooling: 8 chunks of 128 nodes
#define PCH 128
#define SMEM_P ((PCH*32 + PCH*64 + PCH*32) * 4)   // 65536

__device__ __forceinline__ unsigned short f2bf(float f) {
    return __bfloat16_as_ushort(__float2bfloat16(f));
}
__device__ __forceinline__ float bf2f(unsigned short u) {
    return __bfloat162float(__ushort_as_bfloat16(u));
}

// ---------------- scratch (device globals; allocation-free) ----------------
__device__ float          g_dinv[ROWS];
__device__ unsigned       g_adjb[ROWS*32];
__device__ unsigned       g_adjl[ROWS*32];
__device__ int            g_nz[ROWS];
__device__ float          g_h[ROWS*HH];
__device__ float          g_unary[ROWS*CC];
__device__ float          g_e[ROWS*KK];
__device__ float          g_Qa[ROWS*CC];
__device__ float          g_Qb[ROWS*CC];
__device__ float          g_csp[(ROWS/8)*64];
__device__ float          g_cs[BB*64];
__device__ float          g_AQ[ROWS*CC];
__device__ float          g_poolp[(size_t)BB*8*3072];
__device__ unsigned short g_dYT_hi[(size_t)BB*64*NN];   // [b][c][n] bf16
__device__ unsigned short g_dYT_lo[(size_t)BB*64*NN];
__device__ unsigned short g_QT_hi[(size_t)BB*32*NN];
__device__ unsigned short g_QT_lo[(size_t)BB*32*NN];

__device__ __forceinline__ const float* qsel(int s) { return s ? g_Qb : g_Qa; }
__device__ __forceinline__ float*       qselw(int s){ return s ? g_Qb : g_Qa; }

// ------------- K1: pack adjacency bits + degree -> dinv ---------------------
__global__ void k_bits(const int* __restrict__ adj) {
    int warp = threadIdx.x >> 5, lane = threadIdx.x & 31;
    int row  = blockIdx.x * 8 + warp;
    const int* ar = adj + (size_t)row * NN;
    unsigned myw = 0;
#pragma unroll
    for (int w = 0; w < 32; w++) {
        unsigned bal = __ballot_sync(FULLM, ar[(w << 5) + lane] != 0);
        if (lane == w) myw = bal;
    }
    g_adjb[row * 32 + lane] = myw;
    int d = __popc(myw);
#pragma unroll
    for (int o = 16; o; o >>= 1) d += __shfl_xor_sync(FULLM, d, o);
    if (lane == 0) g_dinv[row] = rsqrtf((float)d + 1.0f);
}

// ------------- K2: dYT hi/lo = transpose((x @ W_gcn)*dinv) via WMMA ---------
__global__ void __launch_bounds__(256, 1) k_xw_wmma(const float* __restrict__ x,
                                                    const float* __restrict__ Wg) {
    extern __shared__ char smem[];
    __nv_bfloat16* Ah = (__nv_bfloat16*)smem;      // [TMX][LDX]
    __nv_bfloat16* Al = Ah + TMX * LDX;
    __nv_bfloat16* Bh = Al + TMX * LDX;            // [FF][LDW]
    __nv_bfloat16* Bl = Bh + FF * LDW;
    float* Cs = (float*)smem;                      // alias (epilogue)

    int t = threadIdx.x, w = t >> 5;
    int rowbase = blockIdx.x * TMX;

    for (int i = t; i < FF * HH; i += 256) {
        float v = Wg[i];
        unsigned short hv = f2bf(v);
        int r = i >> 6, c = i & 63;
        Bh[r * LDW + c] = __ushort_as_bfloat16(hv);
        Bl[r * LDW + c] = __ushort_as_bfloat16(f2bf(v - bf2f(hv)));
    }
    {
        const float4* xs = (const float4*)(x + (size_t)rowbase * FF);
        for (int i = t; i < TMX * FF / 4; i += 256) {
            float4 v = xs[i];
            int r = i >> 5, c4 = (i & 31) * 4;
            unsigned short h0 = f2bf(v.x), h1 = f2bf(v.y), h2 = f2bf(v.z), h3 = f2bf(v.w);
            __nv_bfloat16* ah = Ah + r * LDX + c4;
            __nv_bfloat16* al = Al + r * LDX + c4;
            ah[0] = __ushort_as_bfloat16(h0); al[0] = __ushort_as_bfloat16(f2bf(v.x - bf2f(h0)));
            ah[1] = __ushort_as_bfloat16(h1); al[1] = __ushort_as_bfloat16(f2bf(v.y - bf2f(h1)));
            ah[2] = __ushort_as_bfloat16(h2); al[2] = __ushort_as_bfloat16(f2bf(v.z - bf2f(h2)));
            ah[3] = __ushort_as_bfloat16(h3); al[3] = __ushort_as_bfloat16(f2bf(v.w - bf2f(h3)));
        }
    }
    __syncthreads();

    wmma::fragment<wmma::accumulator, 16, 16, 16, float> acc[4];
#pragma unroll
    for (int j = 0; j < 4; j++) wmma::fill_fragment(acc[j], 0.0f);
#pragma unroll
    for (int kt = 0; kt < 8; kt++) {
        wmma::fragment<wmma::matrix_a, 16, 16, 16, __nv_bfloat16, wmma::row_major> ah, al;
        wmma::load_matrix_sync(ah, Ah + (w * 16) * LDX + kt * 16, LDX);
        wmma::load_matrix_sync(al, Al + (w * 16) * LDX + kt * 16, LDX);
#pragma unroll
        for (int j = 0; j < 4; j++) {
            wmma::fragment<wmma::matrix_b, 16, 16, 16, __nv_bfloat16, wmma::row_major> bh, bl;
            wmma::load_matrix_sync(bh, Bh + kt * 16 * LDW + j * 16, LDW);
            wmma::load_matrix_sync(bl, Bl + kt * 16 * LDW + j * 16, LDW);
            wmma::mma_sync(acc[j], ah, bh, acc[j]);
            wmma::mma_sync(acc[j], ah, bl, acc[j]);
            wmma::mma_sync(acc[j], al, bh, acc[j]);
        }
    }
    __syncthreads();
#pragma unroll
    for (int j = 0; j < 4; j++)
        wmma::store_matrix_sync(Cs + (w * 16) * LDCX + j * 16, acc[j], LDCX, wmma::mem_row_major);
    __syncthreads();

    // epilogue: transposed bf16 hi/lo of dY = C*dinv (TMX tile within one batch)
    {
        int c = t >> 2, ns = (t & 3) * 32;
        int b = rowbase >> 10;
        int nb = (rowbase & 1023) + ns;
#pragma unroll 8
        for (int i = 0; i < 32; i++) {
            float v = Cs[(ns + i) * LDCX + c] * g_dinv[rowbase + ns + i];
            unsigned short hv = f2bf(v);
            size_t o = ((size_t)b * 64 + c) * NN + nb + i;
            g_dYT_hi[o] = hv;
            g_dYT_lo[o] = f2bf(v - bf2f(hv));
        }
    }
}

// ------------- K3: 2-hop reachability bitsets + zero counts -----------------
__global__ void k_adjl() {
    int warp = threadIdx.x >> 5, lane = threadIdx.x & 31;
    int row  = blockIdx.x * 8 + warp;
    int base = (row >> 10) << 10;
    unsigned myw = g_adjb[row * 32 + lane];
    unsigned acc = 0;
    for (int wk = 0; wk < 32; wk++) {
        unsigned bits = __shfl_sync(FULLM, myw, wk);
        while (bits) {
            int t = __ffs(bits) - 1; bits &= bits - 1;
            acc |= g_adjb[(size_t)(base + (wk << 5) + t) * 32 + lane];
        }
        if (__all_sync(FULLM, acc == FULLM)) break;
    }
    g_adjl[row * 32 + lane] = acc;
    int nz = __popc(~acc);
#pragma unroll
    for (int o = 16; o; o >>= 1) nz += __shfl_xor_sync(FULLM, nz, o);
    if (lane == 0) g_nz[row] = nz;
}

// ------------- helper: expand 64 adjacency bits into a bf16 smem row --------
__device__ __forceinline__ void expand_row(__nv_bfloat16* As, int t, unsigned w0, unsigned w1) {
    uint4* dst = (uint4*)(As + t * LDA);
#pragma unroll
    for (int seg = 0; seg < 8; seg++) {
        unsigned byte = ((seg < 4) ? (w0 >> (seg * 8)) : (w1 >> ((seg - 4) * 8))) & 0xFFu;
        uint4 v;
        v.x = ((byte & 1u)  ? 0x3F80u : 0u) | ((byte & 2u)   ? 0x3F800000u : 0u);
        v.y = ((byte & 4u)  ? 0x3F80u : 0u) | ((byte & 8u)   ? 0x3F800000u : 0u);
        v.z = ((byte & 16u) ? 0x3F80u : 0u) | ((byte & 32u)  ? 0x3F800000u : 0u);
        v.w = ((byte & 64u) ? 0x3F80u : 0u) | ((byte & 128u) ? 0x3F800000u : 0u);
        dst[seg] = v;
    }
}

// ------------- K4: GCN aggregate via WMMA; self-loop folded into A ----------
__global__ void __launch_bounds__(256, 1) k_gcn_wmma(const float* __restrict__ bg) {
    extern __shared__ char smem[];
    __nv_bfloat16* As  = (__nv_bfloat16*)smem;            // [256][LDA]
    __nv_bfloat16* Bhi = As + TM * LDA;                   // [64][LDB]
    __nv_bfloat16* Blo = Bhi + 64 * LDB;
    float* Cs = (float*)smem;                             // alias (epilogue)

    int t = threadIdx.x, w = t >> 5;
    int wm = w & 3, wn = w >> 2;
    int rowbase = blockIdx.x * TM;
    int b = blockIdx.x >> 2;
    int nloc = (rowbase + t) & 1023;                      // node index within batch

    wmma::fragment<wmma::accumulator, 16, 16, 16, float> acc[4][2];
#pragma unroll
    for (int i = 0; i < 4; i++)
#pragma unroll
        for (int j = 0; j < 2; j++) wmma::fill_fragment(acc[i][j], 0.0f);

    const unsigned* arow = g_adjb + (size_t)(rowbase + t) * 32;
    const unsigned short* ph = g_dYT_hi + (size_t)b * 64 * NN;
    const unsigned short* pl = g_dYT_lo + (size_t)b * 64 * NN;

    unsigned nw0 = arow[0], nw1 = arow[1];
    uint4 nbh[2], nbl[2];
#pragma unroll
    for (int q = 0; q < 2; q++) {
        int j = t + q * 256, c = j >> 3, seg = j & 7;
        size_t go = (size_t)c * NN + seg * 8;
        nbh[q] = *(const uint4*)(ph + go);
        nbl[q] = *(const uint4*)(pl + go);
    }

    for (int kc = 0; kc < 16; kc++) {
        unsigned w0 = nw0, w1 = nw1;
        uint4 bh[2] = { nbh[0], nbh[1] }, bl[2] = { nbl[0], nbl[1] };
        __syncthreads();
        expand_row(As, t, w0, w1);
        // fold self-loop: diagonal of A_hat = adj[ii] + 1  (1.0 or 2.0)
        {
            int nl = nloc - kc * 64;
            if (nl >= 0 && nl < 64) {
                unsigned bit = (nl < 32) ? ((w0 >> nl) & 1u) : ((w1 >> (nl - 32)) & 1u);
                As[t * LDA + nl] = __ushort_as_bfloat16((unsigned short)(bit ? 0x4000 : 0x3F80));
            }
        }
#pragma unroll
        for (int q = 0; q < 2; q++) {
            int j = t + q * 256, c = j >> 3, seg = j & 7;
            *(uint4*)(Bhi + c * LDB + seg * 8) = bh[q];
            *(uint4*)(Blo + c * LDB + seg * 8) = bl[q];
        }
        if (kc < 15) {
            nw0 = arow[(kc + 1) * 2];
            nw1 = arow[(kc + 1) * 2 + 1];
#pragma unroll
            for (int q = 0; q < 2; q++) {
                int j = t + q * 256, c = j >> 3, seg = j & 7;
                size_t go = (size_t)c * NN + (kc + 1) * 64 + seg * 8;
                nbh[q] = *(const uint4*)(ph + go);
                nbl[q] = *(const uint4*)(pl + go);
            }
        }
        __syncthreads();

#pragma unroll
        for (int kt = 0; kt < 4; kt++) {
            wmma::fragment<wmma::matrix_a, 16, 16, 16, __nv_bfloat16, wmma::row_major> af[4];
#pragma unroll
            for (int i = 0; i < 4; i++)
                wmma::load_matrix_sync(af[i], As + (wm * 64 + i * 16) * LDA + kt * 16, LDA);
#pragma unroll
            for (int j = 0; j < 2; j++) {
                wmma::fragment<wmma::matrix_b, 16, 16, 16, __nv_bfloat16, wmma::col_major> bfh, bfl;
                wmma::load_matrix_sync(bfh, Bhi + (wn * 32 + j * 16) * LDB + kt * 16, LDB);
                wmma::load_matrix_sync(bfl, Blo + (wn * 32 + j * 16) * LDB + kt * 16, LDB);
#pragma unroll
                for (int i = 0; i < 4; i++) {
                    wmma::mma_sync(acc[i][j], af[i], bfh, acc[i][j]);
                    wmma::mma_sync(acc[i][j], af[i], bfl, acc[i][j]);
                }
            }
        }
    }

    __syncthreads();
#pragma unroll
    for (int i = 0; i < 4; i++)
#pragma unroll
        for (int j = 0; j < 2; j++)
            wmma::store_matrix_sync(Cs + (wm * 64 + i * 16) * LDC_G + (wn * 32 + j * 16),
                                    acc[i][j], LDC_G, wmma::mem_row_major);
    __syncthreads();

    int r = rowbase + t;
    float di = g_dinv[r];
    float4* hr = (float4*)&g_h[(size_t)r * HH];
#pragma unroll
    for (int i = 0; i < 16; i++) {
        float4 o;
        o.x = fmaxf(fmaf(Cs[t * LDC_G + 4*i+0], di, bg[4*i+0]), 0.f);
        o.y = fmaxf(fmaf(Cs[t * LDC_G + 4*i+1], di, bg[4*i+1]), 0.f);
        o.z = fmaxf(fmaf(Cs[t * LDC_G + 4*i+2], di, bg[4*i+2]), 0.f);
        o.w = fmaxf(fmaf(Cs[t * LDC_G + 4*i+3], di, bg[4*i+3]), 0.f);
        hr[i] = o;
    }
}

// ------------- K5: unary + e + initial softmax + colsum partials ------------
__global__ void k_unary_e(const float* __restrict__ Wu, const float* __restrict__ bu,
                          const float* __restrict__ means, const float* __restrict__ scales) {
    __shared__ float sW[HH * CC];
    __shared__ float sM[KK * HH], sS[KK * HH];
    __shared__ float sp[8][64];
    for (int i = threadIdx.x; i < HH * CC; i += 256) sW[i] = Wu[i];
    for (int i = threadIdx.x; i < KK * HH; i += 256) { sM[i] = means[i]; sS[i] = scales[i]; }
    __syncthreads();
    int warp = threadIdx.x >> 5, lane = threadIdx.x & 31;
    int row  = blockIdx.x * 8 + warp;
    float h0 = g_h[(size_t)row * HH + lane];
    float h1 = g_h[(size_t)row * HH + lane + 32];
    float acc = bu[lane];
#pragma unroll
    for (int hh = 0; hh < HH; hh++) {
        float hv = __shfl_sync(FULLM, (hh < 32) ? h0 : h1, hh & 31);
        acc += hv * sW[hh * CC + lane];
    }
    g_unary[row * CC + lane] = acc;
    float ek[2];
#pragma unroll
    for (int k = 0; k < KK; k++) {
        float d0 = (h0 - sM[k * HH + lane])      / sS[k * HH + lane];
        float d1 = (h1 - sM[k * HH + lane + 32]) / sS[k * HH + lane + 32];
        float s = d0 * d0 + d1 * d1;
#pragma unroll
        for (int o = 16; o; o >>= 1) s += __shfl_xor_sync(FULLM, s, o);
        s = __shfl_sync(FULLM, s, 0);
        ek[k] = expf(-s);
        if (lane == 0) g_e[row * KK + k] = ek[k];
    }
    float m = acc;
#pragma unroll
    for (int o = 16; o; o >>= 1) m = fmaxf(m, __shfl_xor_sync(FULLM, m, o));
    float ex = expf(acc - m);
    float s = ex;
#pragma unroll
    for (int o = 16; o; o >>= 1) s += __shfl_xor_sync(FULLM, s, o);
    float q = ex / s;
    g_Qa[row * CC + lane] = q;
    sp[warp][lane]      = ek[0] * q;
    sp[warp][32 + lane] = ek[1] * q;
    __syncthreads();
    int t = threadIdx.x;
    if (t < 64) {
        float v = 0.f;
#pragma unroll
        for (int w = 0; w < 8; w++) v += sp[w][t];
        g_csp[blockIdx.x * 64 + t] = v;
    }
}

// ------------- CRF reduce: cs[k][c] = (sum partials) @ mu --------------------
__global__ void k_csr(const float* __restrict__ mu) {
    __shared__ float sMu[CC * CC];
    int b = blockIdx.x, t = threadIdx.x, lane = t & 31;   // 64 threads
    for (int i = t; i < CC * CC; i += 64) sMu[i] = mu[i];
    __syncthreads();
    float tv = 0.f;
    for (int i = 0; i < 128; i++) tv += g_csp[(b * 128 + i) * 64 + t];
    float cs = 0.f;
#pragma unroll
    for (int i = 0; i < 32; i++) {
        float ti = __shfl_sync(FULLM, tv, i);
        cs = fmaf(ti, sMu[i * 32 + lane], cs);
    }
    g_cs[b * 64 + t] = cs;
}

// ------------- CRF msg + softmax + colsum partials; last emits QT -----------
__global__ void k_msg(const float* __restrict__ kw, const float* __restrict__ mu,
                      int sel, int last) {
    const float* Qin = qsel(sel);
    float* Qout = qselw(sel ^ 1);
    __shared__ float sp[8][64];
    int warp = threadIdx.x >> 5, lane = threadIdx.x & 31;
    int row  = blockIdx.x * 8 + warp;
    int b    = row >> 10;
    int base = b << 10;
    float z0 = g_cs[b * 64 + lane], z1 = g_cs[b * 64 + 32 + lane];
    int nz = g_nz[row];
    if (__any_sync(FULLM, nz > 0)) {
        unsigned myz = ~g_adjl[row * 32 + lane];
        for (int wk = 0; wk < 32; wk++) {
            unsigned bits = __shfl_sync(FULLM, myz, wk);
            while (bits) {
                int t = __ffs(bits) - 1; bits &= bits - 1;
                int j = base + (wk << 5) + t;
                float qj = Qin[j * CC + lane];
                float p = 0.f;
#pragma unroll
                for (int c = 0; c < CC; c++)
                    p += __shfl_sync(FULLM, qj, c) * mu[c * CC + lane];
                z0 -= g_e[j * KK]     * p;
                z1 -= g_e[j * KK + 1] * p;
            }
        }
    }
    float e0r = g_e[row * KK], e1r = g_e[row * KK + 1];
    float logit = (g_unary[row * CC + lane] + e0r * kw[0] * z0 + e1r * kw[1] * z1) * INV_TEMP;
    float m = logit;
#pragma unroll
    for (int o = 16; o; o >>= 1) m = fmaxf(m, __shfl_xor_sync(FULLM, m, o));
    float ex = expf(logit - m);
    float s = ex;
#pragma unroll
    for (int o = 16; o; o >>= 1) s += __shfl_xor_sync(FULLM, s, o);
    float q = ex / s;
    Qout[row * CC + lane] = q;
    if (last) {
        int n = row & 1023;
        unsigned short hv = f2bf(q);
        size_t o = ((size_t)b * 32 + lane) * NN + n;
        g_QT_hi[o] = hv;
        g_QT_lo[o] = f2bf(q - bf2f(hv));
    } else {
        sp[warp][lane]      = e0r * q;
        sp[warp][32 + lane] = e1r * q;
        __syncthreads();
        int t = threadIdx.x;
        if (t < 64) {
            float v = 0.f;
#pragma unroll
            for (int w = 0; w < 8; w++) v += sp[w][t];
            g_csp[blockIdx.x * 64 + t] = v;
        }
    }
}

// ------------- K7: AQ = adj @ Q via WMMA bf16 hi+lo split -------------------
__global__ void __launch_bounds__(256, 1) k_aq_wmma() {
    extern __shared__ char smem[];
    __nv_bfloat16* As  = (__nv_bfloat16*)smem;            // [256][LDA]
    __nv_bfloat16* Bhi = As + TM * LDA;                   // [32][LDB]
    __nv_bfloat16* Blo = Bhi + 32 * LDB;
    float* Cs = (float*)smem;

    int t = threadIdx.x, w = t >> 5;
    int wm = w & 3, wn = w >> 2;
    int rowbase = blockIdx.x * TM;
    int b = blockIdx.x >> 2;

    wmma::fragment<wmma::accumulator, 16, 16, 16, float> acc[4];
#pragma unroll
    for (int i = 0; i < 4; i++) wmma::fill_fragment(acc[i], 0.0f);

    const unsigned* arow = g_adjb + (size_t)(rowbase + t) * 32;
    const unsigned short* ph = g_QT_hi + (size_t)b * 32 * NN;
    const unsigned short* pl = g_QT_lo + (size_t)b * 32 * NN;

    unsigned nw0 = arow[0], nw1 = arow[1];
    uint4 nbh, nbl;
    {
        int c = t >> 3, seg = t & 7;
        size_t go = (size_t)c * NN + seg * 8;
        nbh = *(const uint4*)(ph + go);
        nbl = *(const uint4*)(pl + go);
    }

    for (int kc = 0; kc < 16; kc++) {
        unsigned w0 = nw0, w1 = nw1;
        uint4 bh = nbh, bl = nbl;
        __syncthreads();
        expand_row(As, t, w0, w1);
        {
            int c = t >> 3, seg = t & 7;
            *(uint4*)(Bhi + c * LDB + seg * 8) = bh;
            *(uint4*)(Blo + c * LDB + seg * 8) = bl;
        }
        if (kc < 15) {
            nw0 = arow[(kc + 1) * 2];
            nw1 = arow[(kc + 1) * 2 + 1];
            int c = t >> 3, seg = t & 7;
            size_t go = (size_t)c * NN + (kc + 1) * 64 + seg * 8;
            nbh = *(const uint4*)(ph + go);
            nbl = *(const uint4*)(pl + go);
        }
        __syncthreads();

#pragma unroll
        for (int kt = 0; kt < 4; kt++) {
            wmma::fragment<wmma::matrix_a, 16, 16, 16, __nv_bfloat16, wmma::row_major> af[4];
#pragma unroll
            for (int i = 0; i < 4; i++)
                wmma::load_matrix_sync(af[i], As + (wm * 64 + i * 16) * LDA + kt * 16, LDA);
            wmma::fragment<wmma::matrix_b, 16, 16, 16, __nv_bfloat16, wmma::col_major> bfh, bfl;
            wmma::load_matrix_sync(bfh, Bhi + (wn * 16) * LDB + kt * 16, LDB);
            wmma::load_matrix_sync(bfl, Blo + (wn * 16) * LDB + kt * 16, LDB);
#pragma unroll
            for (int i = 0; i < 4; i++) {
                wmma::mma_sync(acc[i], af[i], bfh, acc[i]);
                wmma::mma_sync(acc[i], af[i], bfl, acc[i]);
            }
        }
    }

    __syncthreads();
#pragma unroll
    for (int i = 0; i < 4; i++)
        wmma::store_matrix_sync(Cs + (wm * 64 + i * 16) * LDC_A + wn * 16,
                                acc[i], LDC_A, wmma::mem_row_major);
    __syncthreads();

    int r = rowbase + t;
    float4* ar = (float4*)&g_AQ[(size_t)r * CC];
#pragma unroll
    for (int i = 0; i < 8; i++)
        ar[i] = make_float4(Cs[t * LDC_A + 4*i+0], Cs[t * LDC_A + 4*i+1],
                            Cs[t * LDC_A + 4*i+2], Cs[t * LDC_A + 4*i+3]);
}

// ------------- K8a: pooled outputs, 128-node chunks -------------------------
__global__ void __launch_bounds__(256, 1) k_poolp(int sel) {
    const float* Qf = qsel(sel);
    extern __shared__ float psm[];
    float* Qs = psm;                 // [PCH*32]
    float* hs = Qs + PCH * 32;       // [PCH*64]
    float* Aq = hs + PCH * 64;       // [PCH*32]
    int b = blockIdx.x, nc = blockIdx.y;
    int tid = threadIdx.x;
    int n0 = b * NN + nc * PCH;
    {
        const float4* sq = (const float4*)(Qf   + (size_t)n0 * CC);
        const float4* sh = (const float4*)(g_h  + (size_t)n0 * HH);
        const float4* sa = (const float4*)(g_AQ + (size_t)n0 * CC);
#pragma unroll
        for (int q = 0; q < 4; q++) {
            ((float4*)Qs)[tid + q * 256] = sq[tid + q * 256];
            ((float4*)Aq)[tid + q * 256] = sa[tid + q * 256];
        }
#pragma unroll
        for (int q = 0; q < 8; q++) ((float4*)hs)[tid + q * 256] = sh[tid + q * 256];
    }
    __syncthreads();
    int tx = tid & 15, ty = tid >> 4;
    float xp[2][4] = {};
    float ap[2][2] = {};
    for (int n = 0; n < PCH; n++) {
        float q0 = Qs[n * 32 + ty * 2], q1 = Qs[n * 32 + ty * 2 + 1];
        float4 hv = *(const float4*)&hs[n * 64 + tx * 4];
        float a0 = Aq[n * 32 + tx * 2], a1 = Aq[n * 32 + tx * 2 + 1];
        xp[0][0] += q0 * hv.x; xp[0][1] += q0 * hv.y; xp[0][2] += q0 * hv.z; xp[0][3] += q0 * hv.w;
        xp[1][0] += q1 * hv.x; xp[1][1] += q1 * hv.y; xp[1][2] += q1 * hv.z; xp[1][3] += q1 * hv.w;
        ap[0][0] += q0 * a0; ap[0][1] += q0 * a1;
        ap[1][0] += q1 * a0; ap[1][1] += q1 * a1;
    }
    float* dst = g_poolp + ((size_t)b * 8 + nc) * 3072;
#pragma unroll
    for (int cc = 0; cc < 2; cc++) {
#pragma unroll
        for (int c4 = 0; c4 < 4; c4++)
            dst[(ty * 2 + cc) * 64 + tx * 4 + c4] = xp[cc][c4];
#pragma unroll
        for (int a = 0; a < 2; a++)
            dst[2048 + (ty * 2 + cc) * 32 + tx * 2 + a] = ap[cc][a];
    }
}

// ------------- K8b: reduce pooling partials ---------------------------------
__global__ void k_poolred(float* __restrict__ out) {
    int b = blockIdx.x;
    int idx = blockIdx.y * 256 + threadIdx.x;
    float s = 0.f;
    for (int ch = 0; ch < 8; ch++) s += g_poolp[((size_t)b * 8 + ch) * 3072 + idx];
    if (idx < 2048) {
        int c = idx >> 6, hcol = idx & 63;
        out[((size_t)b * CC + c) * HH + hcol] = s;
    } else {
        int j = idx - 2048, c = j >> 5, a = j & 31;
        out[(size_t)BB * CC * HH + ((size_t)b * CC + c) * CC + a] = s;
    }
}

// ---------------------------------------------------------------------------
extern "C" void kernel_launch(void* const* d_in, const int* in_sizes, int n_in,
                              void* d_out, int out_size) {
    const float* x      = (const float*)d_in[0];
    const int*   adj    = (const int*)  d_in[1];
    const float* Wg     = (const float*)d_in[2];
    const float* bg     = (const float*)d_in[3];
    const float* Wu     = (const float*)d_in[4];
    const float* bu     = (const float*)d_in[5];
    const float* means  = (const float*)d_in[6];
    const float* scales = (const float*)d_in[7];
    const float* kw     = (const float*)d_in[8];
    const float* mu     = (const float*)d_in[9];
    float* out = (float*)d_out;

    cudaFuncSetAttribute(k_xw_wmma,  cudaFuncAttributeMaxDynamicSharedMemorySize, SMEM_X);
    cudaFuncSetAttribute(k_gcn_wmma, cudaFuncAttributeMaxDynamicSharedMemorySize, SMEM_WG);
    cudaFuncSetAttribute(k_aq_wmma,  cudaFuncAttributeMaxDynamicSharedMemorySize, SMEM_WA);
    cudaFuncSetAttribute(k_poolp,    cudaFuncAttributeMaxDynamicSharedMemorySize, SMEM_P);

    k_bits     <<<ROWS / 8,   256>>>(adj);
    k_xw_wmma  <<<ROWS / TMX, 256, SMEM_X>>>(x, Wg);
    k_adjl     <<<ROWS / 8,   256>>>();
    k_gcn_wmma <<<ROWS / TM,  256, SMEM_WG>>>(bg);
    k_unary_e  <<<ROWS / 8,   256>>>(Wu, bu, means, scales);

    int sel = 0;
    for (int it = 0; it < NITER; it++) {
        k_csr <<<BB,       64>>>(mu);
        k_msg <<<ROWS / 8, 256>>>(kw, mu, sel, it == NITER - 1);
        sel ^= 1;
    }

    k_aq_wmma <<<ROWS / TM, 256, SMEM_WA>>>();
    k_poolp   <<<dim3(BB, 8), 256, SMEM_P>>>(sel);
    k_poolred <<<dim3(BB, 12), 256>>>(out);
}